// round 1
// baseline (speedup 1.0000x reference)
#include <cuda_runtime.h>

#define Hdim 256
#define Bdim 2048
#define Tdim 512
#define Vdim 64
#define NB   16     // batches per CTA -> 2048/16 = 128 CTAs (1 wave on 148 SMs)

// Scratch (allocation-free rule: __device__ globals)
__device__ float g_P[Vdim * Hdim];      // P[v][o] = sum_h emb[v,h]*W[o,h] + b[o]
__device__ float g_WhT[Hdim * Hdim];    // WhT[k][o] = W[o, 256+k]

// ---------------------------------------------------------------------------
// Precompute kernels (negligible runtime)
// ---------------------------------------------------------------------------
__global__ void k_precompute_P(const float* __restrict__ emb,
                               const float* __restrict__ W,
                               const float* __restrict__ bias) {
    int v = blockIdx.x;          // 0..63
    int o = threadIdx.x;         // 0..255
    const float* e = emb + v * Hdim;
    const float* w = W + o * (2 * Hdim);   // row o of W, first H cols = Wx[o,:]
    float acc = bias[o];
#pragma unroll 8
    for (int h = 0; h < Hdim; ++h) acc += e[h] * w[h];
    g_P[v * Hdim + o] = acc;
}

__global__ void k_transpose_Wh(const float* __restrict__ W) {
    int k = blockIdx.x;          // 0..255
    int o = threadIdx.x;         // 0..255
    g_WhT[k * Hdim + o] = W[o * (2 * Hdim) + Hdim + k];   // Wh[o,k] = W[o, 256+k]
}

// ---------------------------------------------------------------------------
// Packed f32x2 helpers (sm_103a; ptxas will not auto-fuse — must use PTX)
// ---------------------------------------------------------------------------
__device__ __forceinline__ void ffma2(unsigned long long& d,
                                      unsigned long long a,
                                      unsigned long long b) {
    asm("fma.rn.f32x2 %0, %1, %2, %0;" : "+l"(d) : "l"(a), "l"(b));
}
__device__ __forceinline__ unsigned long long pack2(float lo, float hi) {
    unsigned long long r;
    asm("mov.b64 %0, {%1, %2};" : "=l"(r) : "f"(lo), "f"(hi));
    return r;
}
__device__ __forceinline__ void unpack2(unsigned long long v, float& lo, float& hi) {
    asm("mov.b64 {%0, %1}, %2;" : "=f"(lo), "=f"(hi) : "l"(v));
}
__device__ __forceinline__ float sigmoidf(float x) {
    return __fdividef(1.0f, 1.0f + __expf(-x));   // EX2 + RCP (MUFU), err ~2^-21
}

// ---------------------------------------------------------------------------
// Main recurrent kernel.
//
// Thread layout (256 threads): oq = tid>>2 (64 output-quads, 4 outputs each),
//                              bq = tid&3  (4 batch-quads, 4 batches each).
// Accumulators: acc[op][bj] : f32x2 over output pairs (o0+2op, o0+2op+1),
//               one per local batch bj. 8 accumulators, 8 FFMA2 per k.
// h lives in shared memory DUPLICATED: hbuf[k*32 + 2b + {0,1}] both = h[b][k],
// so an LDS.128 yields two broadcast-ready f32x2 operands with zero MOVs.
// Wh is read from L1/L2 as LDG.128; a float4 reinterpreted as ulonglong2
// yields the two f32x2 multiplier pairs with zero MOVs.
// ---------------------------------------------------------------------------
__global__ __launch_bounds__(256, 1) void k_rnn(const int* __restrict__ tokens,
                                                const float* __restrict__ h0,
                                                float* __restrict__ out) {
    extern __shared__ float smem[];                     // 2 * 256*32 floats = 64 KiB
    float* hcur = smem;
    float* hnxt = smem + Hdim * NB * 2;

    const int tid = threadIdx.x;
    const int oq = tid >> 2;            // 0..63
    const int bq = tid & 3;             // 0..3
    const int o0 = oq * 4;
    const int bbase = blockIdx.x * NB;

    // init h (duplicated) from h0
    for (int i = tid; i < Hdim * NB; i += 256) {
        int k = i >> 4, b = i & 15;
        float v = h0[(size_t)(bbase + b) * Hdim + k];
        hcur[k * 32 + 2 * b]     = v;
        hcur[k * 32 + 2 * b + 1] = v;
    }
    __syncthreads();

    for (int t = 0; t < Tdim; ++t) {
        // ---- init accumulators with xproj = P[token] (bias included) ----
        unsigned long long acc[2][4];
#pragma unroll
        for (int bj = 0; bj < 4; ++bj) {
            int bg = bbase + 4 * bq + bj;
            int tok = tokens[(size_t)bg * Tdim + t];
            const float4 pv = *reinterpret_cast<const float4*>(&g_P[tok * Hdim + o0]);
            acc[0][bj] = pack2(pv.x, pv.y);
            acc[1][bj] = pack2(pv.z, pv.w);
        }

        // ---- recurrent GEMV: acc += h @ Wh^T ----
        const float* hr = hcur + 8 * bq;   // this thread's 4 duplicated h pairs per k-row
#pragma unroll 4
        for (int k = 0; k < Hdim; ++k) {
            // two f32x2 multiplier pairs straight out of one LDG.128
            ulonglong2 w2 = *reinterpret_cast<const ulonglong2*>(&g_WhT[k * Hdim + o0]);
            // four duplicated-h f32x2 operands out of two LDS.128
            ulonglong2 hA = *reinterpret_cast<const ulonglong2*>(&hr[k * 32]);
            ulonglong2 hB = *reinterpret_cast<const ulonglong2*>(&hr[k * 32 + 4]);
            ffma2(acc[0][0], w2.x, hA.x); ffma2(acc[1][0], w2.y, hA.x);
            ffma2(acc[0][1], w2.x, hA.y); ffma2(acc[1][1], w2.y, hA.y);
            ffma2(acc[0][2], w2.x, hB.x); ffma2(acc[1][2], w2.y, hB.x);
            ffma2(acc[0][3], w2.x, hB.y); ffma2(acc[1][3], w2.y, hB.y);
        }

        // ---- sigmoid, write output, stage h_{t+1} (duplicated) ----
        float* outp = out + (size_t)t * (Bdim * Hdim);
#pragma unroll
        for (int bj = 0; bj < 4; ++bj) {
            int bl = 4 * bq + bj;
            float x0, x1, x2, x3;
            unpack2(acc[0][bj], x0, x1);
            unpack2(acc[1][bj], x2, x3);
            float4 sv;
            sv.x = sigmoidf(x0);
            sv.y = sigmoidf(x1);
            sv.z = sigmoidf(x2);
            sv.w = sigmoidf(x3);
            *reinterpret_cast<float4*>(&outp[(size_t)(bbase + bl) * Hdim + o0]) = sv;
            hnxt[(o0 + 0) * 32 + 2 * bl] = sv.x; hnxt[(o0 + 0) * 32 + 2 * bl + 1] = sv.x;
            hnxt[(o0 + 1) * 32 + 2 * bl] = sv.y; hnxt[(o0 + 1) * 32 + 2 * bl + 1] = sv.y;
            hnxt[(o0 + 2) * 32 + 2 * bl] = sv.z; hnxt[(o0 + 2) * 32 + 2 * bl + 1] = sv.z;
            hnxt[(o0 + 3) * 32 + 2 * bl] = sv.w; hnxt[(o0 + 3) * 32 + 2 * bl + 1] = sv.w;
        }
        __syncthreads();
        float* tmp = hcur; hcur = hnxt; hnxt = tmp;
    }
}

// ---------------------------------------------------------------------------
// Harness entry
// Inputs (metadata order): tokens(int32 2048x512), h0(f32 2048x256),
//                          emb(f32 64x256), W(f32 256x512), b(f32 256)
// Output: f32 (512, 2048, 256)
// ---------------------------------------------------------------------------
extern "C" void kernel_launch(void* const* d_in, const int* in_sizes, int n_in,
                              void* d_out, int out_size) {
    const int*   tokens = (const int*)d_in[0];
    const float* h0     = (const float*)d_in[1];
    const float* emb    = (const float*)d_in[2];
    const float* W      = (const float*)d_in[3];
    const float* bias   = (const float*)d_in[4];
    float*       out    = (float*)d_out;

    (void)in_sizes; (void)n_in; (void)out_size;

    k_precompute_P<<<Vdim, Hdim>>>(emb, W, bias);
    k_transpose_Wh<<<Hdim, Hdim>>>(W);

    const int smem_bytes = 2 * Hdim * NB * 2 * (int)sizeof(float);   // 65536
    cudaFuncSetAttribute(k_rnn, cudaFuncAttributeMaxDynamicSharedMemorySize, smem_bytes);
    k_rnn<<<Bdim / NB, 256, smem_bytes>>>(tokens, h0, out);
}